// round 11
// baseline (speedup 1.0000x reference)
#include <cuda_runtime.h>
#include <cuda_bf16.h>
#include <cstdint>

#define N_ITEMS  262144
#define DIM      128
#define NCB      3
#define KCW      256
#define TM       128
#define NTILES   (N_ITEMS / TM)   // 2048
#define NTHREADS 512
#define GRID     148
#define MARGIN   1.0e-2f
#define CAP      8
#define STB      528              // smem row stride bytes (264 bf16)

__device__ float g_cc[NCB * KCW];
__device__ float g_res[(size_t)N_ITEMS * DIM];
__device__ int   g_idx[2 * N_ITEMS];

__device__ __forceinline__ uint32_t s2u(const void* p) {
    return (uint32_t)__cvta_generic_to_shared(p);
}
#define LDSM4(r0,r1,r2,r3,a) asm volatile("ldmatrix.sync.aligned.m8n8.x4.shared.b16 {%0,%1,%2,%3}, [%4];" : "=r"(r0),"=r"(r1),"=r"(r2),"=r"(r3) : "r"(a))
#define MMA16816(d,a0,a1,a2,a3,b0,b1) asm volatile( \
    "mma.sync.aligned.m16n8k16.row.col.f32.bf16.bf16.f32 " \
    "{%0,%1,%2,%3}, {%4,%5,%6,%7}, {%8,%9}, {%0,%1,%2,%3};" \
    : "+f"((d)[0]),"+f"((d)[1]),"+f"((d)[2]),"+f"((d)[3]) \
    : "r"(a0),"r"(a1),"r"(a2),"r"(a3),"r"(b0),"r"(b1))

// ---- ||c||^2 double sequential chain (validated association) ----
__global__ void cc_kernel(const float* __restrict__ codebooks) {
    int row = blockIdx.x * 32 + threadIdx.x;
    if (row >= NCB * KCW) return;
    const float* r = codebooks + (size_t)row * DIM;
    double s = 0.0;
    #pragma unroll 8
    for (int k = 0; k < DIM; k++) { double v = (double)r[k]; s += v * v; }
    g_cc[row] = (float)s;
}

// ---- exact d2: sequential k-ascending fmaf chain (validated R3-R10) ----
__device__ __noinline__ float exact_d2(const float* __restrict__ r,
                                       const float* __restrict__ c,
                                       float rr, float ccj) {
    float dot = 0.f;
    #pragma unroll
    for (int m = 0; m < 32; m++) {
        float4 a = ((const float4*)r)[m];
        float4 b = ((const float4*)c)[m];
        dot = __fmaf_rn(a.x, b.x, dot);
        dot = __fmaf_rn(a.y, b.y, dot);
        dot = __fmaf_rn(a.z, b.z, dot);
        dot = __fmaf_rn(a.w, b.w, dot);
    }
    return __fadd_rn(__fmaf_rn(-2.f, dot, rr), ccj);
}

__device__ __forceinline__ void split2(float v0, float v1, uint32_t& hi, uint32_t& mi) {
    __nv_bfloat16 h0 = __float2bfloat16(v0), h1 = __float2bfloat16(v1);
    float r0 = v0 - __bfloat162float(h0), r1 = v1 - __bfloat162float(h1);
    __nv_bfloat16 m0 = __float2bfloat16(r0), m1 = __float2bfloat16(r1);
    hi = (uint32_t)__bfloat16_as_ushort(h0) | ((uint32_t)__bfloat16_as_ushort(h1) << 16);
    mi = (uint32_t)__bfloat16_as_ushort(m0) | ((uint32_t)__bfloat16_as_ushort(m1) << 16);
}

// smem offsets (bytes, from 1024-aligned base)
#define O_A     0                     // 128*528 = 67584
#define O_B     67584                 // 256*528 = 135168
#define O_CC    202752                // 1024
#define O_RRS   203776                // 512
#define O_HM    204288                // 2*128*4 = 1024
#define O_CNT   205312                // 512
#define O_CAND  205824                // 128*CAP*4 = 4096
#define O_BEST  209920                // 512
#define SMEM_BYTES (210432 + 1024)

__global__ __launch_bounds__(NTHREADS, 1)
void rvq_kernel(const float* __restrict__ x,
                const float* __restrict__ codebooks,
                float* __restrict__ out, int mode)
{
    extern __shared__ char smraw[];
    char* smem = (char*)(((uintptr_t)smraw + 1023) & ~(uintptr_t)1023);
    float* cc_s = (float*)(smem + O_CC);
    float* rrs  = (float*)(smem + O_RRS);
    float* hm   = (float*)(smem + O_HM);      // [2][128]
    int*   cnt  = (int*)(smem + O_CNT);
    int*   cand = (int*)(smem + O_CAND);      // [128][CAP]
    int*   best = (int*)(smem + O_BEST);

    const int t = threadIdx.x, w = t >> 5, lane = t & 31;
    const uint32_t sA = s2u(smem + O_A), sB = s2u(smem + O_B);
    const int mrow0 = 16 * (w & 7);           // warp's 16-item block
    const int colbase = 128 * (w >> 3);       // warp's 128-cw half

    for (int stage = 0; stage < NCB; stage++) {
        __syncthreads();
        // ---- B conversion: 2 threads per codeword row ----
        {
            int row = t >> 1, h = t & 1;
            const float4* cr = (const float4*)(codebooks + ((size_t)stage * KCW + row) * DIM + h * 64);
            char* hrow = smem + O_B + row * STB + h * 128;
            #pragma unroll
            for (int m = 0; m < 16; m++) {
                float4 v = cr[m];
                uint32_t h0, mi0, h1, mi1;
                split2(v.x, v.y, h0, mi0);
                split2(v.z, v.w, h1, mi1);
                *(uint2*)(hrow + m * 8)       = make_uint2(h0, h1);
                *(uint2*)(hrow + 256 + m * 8) = make_uint2(mi0, mi1);
            }
            if (t < KCW) cc_s[t] = g_cc[stage * KCW + t];
        }
        const float* src = (stage == 0) ? x : g_res;
        __syncthreads();

        for (int tl = blockIdx.x; tl < NTILES; tl += GRID) {
            // ---- phase 1: A conversion + rr + zero cnt ----
            {
                int i = t >> 2, q = t & 3;
                const float4* rg = (const float4*)(src + (size_t)(tl * TM + i) * DIM + q * 32);
                char* arow = smem + O_A + i * STB + q * 64;
                double s = 0.0;
                #pragma unroll
                for (int m = 0; m < 8; m++) {
                    float4 v = rg[m];
                    double a = v.x, b = v.y, c = v.z, d = v.w;
                    s += a * a; s += b * b; s += c * c; s += d * d;
                    uint32_t h0, mi0, h1, mi1;
                    split2(v.x, v.y, h0, mi0);
                    split2(v.z, v.w, h1, mi1);
                    *(uint2*)(arow + m * 8)       = make_uint2(h0, h1);
                    *(uint2*)(arow + 256 + m * 8) = make_uint2(mi0, mi1);
                }
                s += __shfl_xor_sync(0xffffffffu, s, 1);
                s += __shfl_xor_sync(0xffffffffu, s, 2);
                if (q == 0) rrs[i] = (float)s;
                if (t < TM) cnt[t] = 0;
            }
            __syncthreads();

            // ---- phase 2: MMA, 3 passes (hh, hm, mh), B via ldmatrix.x4 ----
            float d[16][4];
            #pragma unroll
            for (int nt = 0; nt < 16; nt++)
                #pragma unroll
                for (int e = 0; e < 4; e++) d[nt][e] = 0.f;

            const uint32_t aAddr0 = sA + (mrow0 + (lane & 15)) * STB + (lane >> 4) * 16;
            // B x4: g=lane>>3: g0 rows ntp*16+(lane&7) k+0 | g1 same +16B | g2 rows+8 k+0 | g3 rows+8 +16B
            const uint32_t bAddr0 = sB + (colbase + ((lane >> 4) & 1) * 8 + (lane & 7)) * STB
                                       + ((lane >> 3) & 1) * 16;
            const int KA[3] = {0, 0, 256};   // byte offsets: mid region at +256
            const int KB[3] = {0, 256, 0};

            #pragma unroll 1
            for (int p = 0; p < 3; p++) {
                uint32_t aBase = aAddr0 + KA[p];
                uint32_t bBase = bAddr0 + KB[p];
                #pragma unroll 1
                for (int ks = 0; ks < 8; ks++) {
                    uint32_t a0, a1, a2, a3;
                    LDSM4(a0, a1, a2, a3, aBase + ks * 32);
                    #pragma unroll
                    for (int ntp = 0; ntp < 8; ntp++) {
                        uint32_t b0, b1, b2, b3;
                        LDSM4(b0, b1, b2, b3, bBase + ntp * 16 * STB + ks * 32);
                        MMA16816(d[2 * ntp],     a0, a1, a2, a3, b0, b1);
                        MMA16816(d[2 * ntp + 1], a0, a1, a2, a3, b2, b3);
                    }
                }
            }

            // ---- phase 3: approx d2 + per-item half-min ----
            const int item0 = mrow0 + (lane >> 2);
            const int item1 = item0 + 8;
            const float rr0 = rrs[item0], rr1 = rrs[item1];
            float mn0 = 3.0e38f, mn1 = 3.0e38f;
            #pragma unroll
            for (int nt = 0; nt < 16; nt++) {
                int n = colbase + nt * 8 + 2 * (lane & 3);
                float c0 = cc_s[n], c1 = cc_s[n + 1];
                d[nt][0] = __fadd_rn(__fmaf_rn(-2.f, d[nt][0], rr0), c0);
                d[nt][1] = __fadd_rn(__fmaf_rn(-2.f, d[nt][1], rr0), c1);
                d[nt][2] = __fadd_rn(__fmaf_rn(-2.f, d[nt][2], rr1), c0);
                d[nt][3] = __fadd_rn(__fmaf_rn(-2.f, d[nt][3], rr1), c1);
                mn0 = fminf(mn0, fminf(d[nt][0], d[nt][1]));
                mn1 = fminf(mn1, fminf(d[nt][2], d[nt][3]));
            }
            mn0 = fminf(mn0, __shfl_xor_sync(0xffffffffu, mn0, 1));
            mn0 = fminf(mn0, __shfl_xor_sync(0xffffffffu, mn0, 2));
            mn1 = fminf(mn1, __shfl_xor_sync(0xffffffffu, mn1, 1));
            mn1 = fminf(mn1, __shfl_xor_sync(0xffffffffu, mn1, 2));
            if ((lane & 3) == 0) {
                hm[(w >> 3) * TM + item0] = mn0;
                hm[(w >> 3) * TM + item1] = mn1;
            }
            __syncthreads();

            // ---- phase 4: candidate collection ----
            {
                float thr0 = fminf(hm[item0], hm[TM + item0]) + MARGIN;
                float thr1 = fminf(hm[item1], hm[TM + item1]) + MARGIN;
                #pragma unroll
                for (int nt = 0; nt < 16; nt++) {
                    int n = colbase + nt * 8 + 2 * (lane & 3);
                    #pragma unroll
                    for (int e = 0; e < 4; e++) {
                        int it = (e < 2) ? item0 : item1;
                        float thr = (e < 2) ? thr0 : thr1;
                        if (d[nt][e] <= thr) {
                            int slot = atomicAdd(&cnt[it], 1);
                            if (slot < CAP) cand[it * CAP + slot] = n + (e & 1);
                        }
                    }
                }
            }
            __syncthreads();

            // ---- phase 5: rescue + decide (t < 128) ----
            if (t < TM) {
                int c = cnt[t], bi;
                if (c == 1) {
                    bi = cand[t * CAP];
                } else {
                    const float* rrow = src + (size_t)(tl * TM + t) * DIM;
                    const float* cb0  = codebooks + (size_t)stage * KCW * DIM;
                    float rr = rrs[t];
                    float bv = 3.0e38f; bi = KCW;
                    if (c <= CAP) {
                        #pragma unroll 1
                        for (int q = 0; q < c; q++) {
                            int j = cand[t * CAP + q];
                            float e = exact_d2(rrow, cb0 + (size_t)j * DIM, rr, cc_s[j]);
                            if (e < bv || (e == bv && j < bi)) { bv = e; bi = j; }
                        }
                    } else {
                        #pragma unroll 1
                        for (int j = 0; j < KCW; j++) {
                            float e = exact_d2(rrow, cb0 + (size_t)j * DIM, rr, cc_s[j]);
                            if (e < bv || (e == bv && j < bi)) { bv = e; bi = j; }
                        }
                    }
                }
                best[t] = bi;
                int gi = tl * TM + t;
                if (stage < 2) g_idx[stage * N_ITEMS + gi] = bi;
                if (mode == 0)      out[(size_t)gi * 3 + stage] = (float)bi;
                else if (mode == 2) ((int*)out)[(size_t)gi * 3 + stage] = bi;
            }
            __syncthreads();

            // ---- phase 6: residual update / quantize ----
            {
                int i = t >> 2, off = (t & 3) * 32;
                int gi = tl * TM + i;
                if (stage < 2) {
                    int bi = best[i];
                    const float4* cr = (const float4*)(codebooks + ((size_t)stage * KCW + bi) * DIM + off);
                    const float4* rg = (const float4*)(src + (size_t)gi * DIM + off);
                    float4* go = (float4*)(g_res + (size_t)gi * DIM + off);
                    #pragma unroll
                    for (int m = 0; m < 8; m++) {
                        float4 r = rg[m], c = cr[m], o;
                        o.x = __fsub_rn(r.x, c.x); o.y = __fsub_rn(r.y, c.y);
                        o.z = __fsub_rn(r.z, c.z); o.w = __fsub_rn(r.w, c.w);
                        go[m] = o;
                    }
                } else if (mode != 2) {
                    int i0 = g_idx[gi], i1 = g_idx[N_ITEMS + gi], i2 = best[i];
                    const float4* c0 = (const float4*)(codebooks + (size_t)i0 * DIM + off);
                    const float4* c1 = (const float4*)(codebooks + ((size_t)KCW + i1) * DIM + off);
                    const float4* c2 = (const float4*)(codebooks + ((size_t)2 * KCW + i2) * DIM + off);
                    float* outq = (mode == 0) ? (out + (size_t)N_ITEMS * 3) : out;
                    float4* go = (float4*)(outq + (size_t)gi * DIM + off);
                    #pragma unroll
                    for (int m = 0; m < 8; m++) {
                        float4 a = c0[m], b = c1[m], c = c2[m], o;
                        o.x = __fadd_rn(__fadd_rn(a.x, b.x), c.x);
                        o.y = __fadd_rn(__fadd_rn(a.y, b.y), c.y);
                        o.z = __fadd_rn(__fadd_rn(a.z, b.z), c.z);
                        o.w = __fadd_rn(__fadd_rn(a.w, b.w), c.w);
                        go[m] = o;
                    }
                }
            }
        }
    }
}

extern "C" void kernel_launch(void* const* d_in, const int* in_sizes, int n_in,
                              void* d_out, int out_size)
{
    const float* x   = (const float*)d_in[0];
    const float* cbk = (const float*)d_in[1];
    if (n_in >= 2 && in_sizes[0] == NCB * KCW * DIM && in_sizes[1] == N_ITEMS * DIM) {
        const float* tmp = x; x = cbk; cbk = tmp;
    }
    int mode;
    if (out_size == N_ITEMS * (3 + DIM))      mode = 0;
    else if (out_size == N_ITEMS * DIM)       mode = 1;
    else if (out_size == N_ITEMS * 3)         mode = 2;
    else                                       mode = (out_size > N_ITEMS * DIM) ? 0 : 1;

    cc_kernel<<<(NCB * KCW + 31) / 32, 32>>>(cbk);
    cudaFuncSetAttribute(rvq_kernel, cudaFuncAttributeMaxDynamicSharedMemorySize, SMEM_BYTES);
    rvq_kernel<<<GRID, NTHREADS, SMEM_BYTES>>>(x, cbk, (float*)d_out, mode);
}

// round 12
// speedup vs baseline: 1.0415x; 1.0415x over previous
#include <cuda_runtime.h>
#include <cuda_bf16.h>
#include <cstdint>

#define N_ITEMS  262144
#define DIM      128
#define NCB      3
#define KCW      256
#define TM       128
#define NTILES   (N_ITEMS / TM)   // 2048
#define NTHREADS 512
#define GRID     148
#define STB      272              // smem row stride bytes (136 bf16)
#define CAPW     3072
#define MCOEF    0.040f           // 2*M coefficient (2 * 2.1 * 2^-8 * 2, slack incl.)

__device__ float g_cc[NCB * KCW];
__device__ int   g_cmax[NCB];     // float bits of max ||c||, atomicMax (monotone)
__device__ float g_res[(size_t)N_ITEMS * DIM];
__device__ int   g_idx[2 * N_ITEMS];

__device__ __forceinline__ uint32_t s2u(const void* p) {
    return (uint32_t)__cvta_generic_to_shared(p);
}
#define LDSM4(r0,r1,r2,r3,a) asm volatile("ldmatrix.sync.aligned.m8n8.x4.shared.b16 {%0,%1,%2,%3}, [%4];" : "=r"(r0),"=r"(r1),"=r"(r2),"=r"(r3) : "r"(a))
#define MMA16816(d,a0,a1,a2,a3,b0,b1) asm volatile( \
    "mma.sync.aligned.m16n8k16.row.col.f32.bf16.bf16.f32 " \
    "{%0,%1,%2,%3}, {%4,%5,%6,%7}, {%8,%9}, {%0,%1,%2,%3};" \
    : "+f"((d)[0]),"+f"((d)[1]),"+f"((d)[2]),"+f"((d)[3]) \
    : "r"(a0),"r"(a1),"r"(a2),"r"(a3),"r"(b0),"r"(b1))
#define CVTBF2(o, lo, hi) asm("cvt.rn.bf16x2.f32 %0, %1, %2;" : "=r"(o) : "f"(hi), "f"(lo))

__device__ __forceinline__ uint32_t ford(float f) {   // order-preserving float->uint
    uint32_t u = __float_as_uint(f);
    return (u & 0x80000000u) ? ~u : (u | 0x80000000u);
}

// ---- ||c||^2 double sequential chain (validated) + per-stage max norm ----
__global__ void cc_kernel(const float* __restrict__ codebooks) {
    int row = blockIdx.x * 32 + threadIdx.x;
    if (row >= NCB * KCW) return;
    const float* r = codebooks + (size_t)row * DIM;
    double s = 0.0;
    #pragma unroll 8
    for (int k = 0; k < DIM; k++) { double v = (double)r[k]; s += v * v; }
    g_cc[row] = (float)s;
    float nrm = sqrtf((float)s) * 1.0001f;
    atomicMax(&g_cmax[row / KCW], __float_as_int(nrm));
}

// ---- exact d2: sequential k-ascending fmaf chain (validated R3-R11) ----
__device__ __noinline__ float exact_d2(const float* __restrict__ r,
                                       const float* __restrict__ c,
                                       float rr, float ccj) {
    float dot = 0.f;
    #pragma unroll
    for (int m = 0; m < 32; m++) {
        float4 a = ((const float4*)r)[m];
        float4 b = ((const float4*)c)[m];
        dot = __fmaf_rn(a.x, b.x, dot);
        dot = __fmaf_rn(a.y, b.y, dot);
        dot = __fmaf_rn(a.z, b.z, dot);
        dot = __fmaf_rn(a.w, b.w, dot);
    }
    return __fadd_rn(__fmaf_rn(-2.f, dot, rr), ccj);
}

// smem offsets (bytes, from 1024-aligned base)
#define O_A     0                     // 128*272 = 34816
#define O_B     34816                 // 256*272 = 69632
#define O_CC    104448                // 1024
#define O_RRS   105472                // 512
#define O_HM    105984                // 1024
#define O_EKEY  107008                // 128*8 = 1024
#define O_WL    108032                // 3072*4 = 12288
#define O_BEST  120320                // 512
#define O_WCNT  120832                // 16
#define SMEM_BYTES (120848 + 1024)

__global__ __launch_bounds__(NTHREADS, 1)
void rvq_kernel(const float* __restrict__ x,
                const float* __restrict__ codebooks,
                float* __restrict__ out, int mode)
{
    extern __shared__ char smraw[];
    char* smem = (char*)(((uintptr_t)smraw + 1023) & ~(uintptr_t)1023);
    float* cc_s = (float*)(smem + O_CC);
    float* rrs  = (float*)(smem + O_RRS);
    float* hm   = (float*)(smem + O_HM);      // [2][128]
    unsigned long long* ekey = (unsigned long long*)(smem + O_EKEY);
    uint32_t* wl = (uint32_t*)(smem + O_WL);
    int*   best = (int*)(smem + O_BEST);
    int*   wcnt = (int*)(smem + O_WCNT);

    const int t = threadIdx.x, w = t >> 5, lane = t & 31;
    const uint32_t sA = s2u(smem + O_A), sB = s2u(smem + O_B);
    const int mrow0 = 16 * (w & 7);           // warp's 16-item block
    const int colbase = 128 * (w >> 3);       // warp's 128-cw half

    for (int stage = 0; stage < NCB; stage++) {
        __syncthreads();
        const float cmax = __int_as_float(g_cmax[stage]);
        // ---- B conversion (hi bf16 only): 2 threads per codeword row ----
        {
            int row = t >> 1, h = t & 1;
            const float4* cr = (const float4*)(codebooks + ((size_t)stage * KCW + row) * DIM + h * 64);
            char* hrow = smem + O_B + row * STB + h * 128;
            #pragma unroll
            for (int m = 0; m < 8; m++) {
                float4 v0 = cr[2 * m], v1 = cr[2 * m + 1];
                uint4 o;
                CVTBF2(o.x, v0.x, v0.y); CVTBF2(o.y, v0.z, v0.w);
                CVTBF2(o.z, v1.x, v1.y); CVTBF2(o.w, v1.z, v1.w);
                *(uint4*)(hrow + m * 16) = o;
            }
            if (t < KCW) cc_s[t] = g_cc[stage * KCW + t];
        }
        const float* src = (stage == 0) ? x : g_res;
        __syncthreads();

        for (int tl = blockIdx.x; tl < NTILES; tl += GRID) {
            // ---- phase 1: A conversion + rr (validated chain) + init ----
            {
                int i = t >> 2, q = t & 3;
                const float4* rg = (const float4*)(src + (size_t)(tl * TM + i) * DIM + q * 32);
                char* arow = smem + O_A + i * STB + q * 64;
                double s = 0.0;
                #pragma unroll
                for (int m = 0; m < 4; m++) {
                    float4 v0 = rg[2 * m], v1 = rg[2 * m + 1];
                    double a = v0.x, b = v0.y, c = v0.z, d = v0.w;
                    s += a * a; s += b * b; s += c * c; s += d * d;
                    double e = v1.x, f = v1.y, g = v1.z, h2 = v1.w;
                    s += e * e; s += f * f; s += g * g; s += h2 * h2;
                    uint4 o;
                    CVTBF2(o.x, v0.x, v0.y); CVTBF2(o.y, v0.z, v0.w);
                    CVTBF2(o.z, v1.x, v1.y); CVTBF2(o.w, v1.z, v1.w);
                    *(uint4*)(arow + m * 16) = o;
                }
                s += __shfl_xor_sync(0xffffffffu, s, 1);
                s += __shfl_xor_sync(0xffffffffu, s, 2);
                if (q == 0) rrs[i] = (float)s;
                if (t < TM) ekey[t] = ~0ull;
                if (t == 0) *wcnt = 0;
            }
            __syncthreads();

            // ---- phase 2: single-pass hi x hi MMA ----
            float d[16][4];
            #pragma unroll
            for (int nt = 0; nt < 16; nt++)
                #pragma unroll
                for (int e = 0; e < 4; e++) d[nt][e] = 0.f;

            const uint32_t aAddr0 = sA + (mrow0 + (lane & 15)) * STB + (lane >> 4) * 16;
            const uint32_t bAddr0 = sB + (colbase + ((lane >> 4) & 1) * 8 + (lane & 7)) * STB
                                       + ((lane >> 3) & 1) * 16;
            #pragma unroll 1
            for (int ks = 0; ks < 8; ks++) {
                uint32_t a0, a1, a2, a3;
                LDSM4(a0, a1, a2, a3, aAddr0 + ks * 32);
                #pragma unroll
                for (int ntp = 0; ntp < 8; ntp++) {
                    uint32_t b0, b1, b2, b3;
                    LDSM4(b0, b1, b2, b3, bAddr0 + ntp * 16 * STB + ks * 32);
                    MMA16816(d[2 * ntp],     a0, a1, a2, a3, b0, b1);
                    MMA16816(d[2 * ntp + 1], a0, a1, a2, a3, b2, b3);
                }
            }

            // ---- phase 3: approx d2 + per-item half-min ----
            const int item0 = mrow0 + (lane >> 2);
            const int item1 = item0 + 8;
            const float rr0 = rrs[item0], rr1 = rrs[item1];
            float mn0 = 3.0e38f, mn1 = 3.0e38f;
            #pragma unroll
            for (int nt = 0; nt < 16; nt++) {
                int n = colbase + nt * 8 + 2 * (lane & 3);
                float c0 = cc_s[n], c1 = cc_s[n + 1];
                d[nt][0] = __fadd_rn(__fmaf_rn(-2.f, d[nt][0], rr0), c0);
                d[nt][1] = __fadd_rn(__fmaf_rn(-2.f, d[nt][1], rr0), c1);
                d[nt][2] = __fadd_rn(__fmaf_rn(-2.f, d[nt][2], rr1), c0);
                d[nt][3] = __fadd_rn(__fmaf_rn(-2.f, d[nt][3], rr1), c1);
                mn0 = fminf(mn0, fminf(d[nt][0], d[nt][1]));
                mn1 = fminf(mn1, fminf(d[nt][2], d[nt][3]));
            }
            mn0 = fminf(mn0, __shfl_xor_sync(0xffffffffu, mn0, 1));
            mn0 = fminf(mn0, __shfl_xor_sync(0xffffffffu, mn0, 2));
            mn1 = fminf(mn1, __shfl_xor_sync(0xffffffffu, mn1, 1));
            mn1 = fminf(mn1, __shfl_xor_sync(0xffffffffu, mn1, 2));
            if ((lane & 3) == 0) {
                hm[(w >> 3) * TM + item0] = mn0;
                hm[(w >> 3) * TM + item1] = mn1;
            }
            __syncthreads();

            // ---- phase 4: candidate collection (2M window, provable) ----
            {
                float thr0 = fminf(hm[item0], hm[TM + item0])
                           + MCOEF * sqrtf(rr0) * cmax + 1e-3f;
                float thr1 = fminf(hm[item1], hm[TM + item1])
                           + MCOEF * sqrtf(rr1) * cmax + 1e-3f;
                #pragma unroll
                for (int nt = 0; nt < 16; nt++) {
                    int n = colbase + nt * 8 + 2 * (lane & 3);
                    #pragma unroll
                    for (int e = 0; e < 4; e++) {
                        int it = (e < 2) ? item0 : item1;
                        float thr = (e < 2) ? thr0 : thr1;
                        if (d[nt][e] <= thr) {
                            int slot = atomicAdd(wcnt, 1);
                            if (slot < CAPW)
                                wl[slot] = ((uint32_t)it << 16) | (uint32_t)(n + (e & 1));
                        }
                    }
                }
            }
            __syncthreads();

            // ---- phase 5: exact evaluation of all candidates, lex-min ----
            {
                int wc = *wcnt;
                const float* cb0 = codebooks + (size_t)stage * KCW * DIM;
                if (wc <= CAPW) {
                    for (int e = t; e < wc; e += NTHREADS) {
                        uint32_t u = wl[e];
                        int it = u >> 16, j = u & 0xffff;
                        float ex = exact_d2(src + (size_t)(tl * TM + it) * DIM,
                                            cb0 + (size_t)j * DIM, rrs[it], cc_s[j]);
                        unsigned long long key = ((unsigned long long)ford(ex) << 32) | (uint32_t)j;
                        atomicMin(&ekey[it], key);
                    }
                } else if (t < TM) {          // overflow fallback: full exact scan
                    float rr = rrs[t];
                    const float* rrow = src + (size_t)(tl * TM + t) * DIM;
                    float bv = 3.0e38f; int bi = KCW;
                    #pragma unroll 1
                    for (int j = 0; j < KCW; j++) {
                        float ex = exact_d2(rrow, cb0 + (size_t)j * DIM, rr, cc_s[j]);
                        if (ex < bv || (ex == bv && j < bi)) { bv = ex; bi = j; }
                    }
                    ekey[t] = ((unsigned long long)ford(bv) << 32) | (uint32_t)bi;
                }
            }
            __syncthreads();

            if (t < TM) {
                int bi = (int)(ekey[t] & 0xffffffffu);
                best[t] = bi;
                int gi = tl * TM + t;
                if (stage < 2) g_idx[stage * N_ITEMS + gi] = bi;
                if (mode == 0)      out[(size_t)gi * 3 + stage] = (float)bi;
                else if (mode == 2) ((int*)out)[(size_t)gi * 3 + stage] = bi;
            }
            __syncthreads();

            // ---- phase 6: residual update / quantize (validated) ----
            {
                int i = t >> 2, off = (t & 3) * 32;
                int gi = tl * TM + i;
                if (stage < 2) {
                    int bi = best[i];
                    const float4* cr = (const float4*)(codebooks + ((size_t)stage * KCW + bi) * DIM + off);
                    const float4* rg = (const float4*)(src + (size_t)gi * DIM + off);
                    float4* go = (float4*)(g_res + (size_t)gi * DIM + off);
                    #pragma unroll
                    for (int m = 0; m < 8; m++) {
                        float4 r = rg[m], c = cr[m], o;
                        o.x = __fsub_rn(r.x, c.x); o.y = __fsub_rn(r.y, c.y);
                        o.z = __fsub_rn(r.z, c.z); o.w = __fsub_rn(r.w, c.w);
                        go[m] = o;
                    }
                } else if (mode != 2) {
                    int i0 = g_idx[gi], i1 = g_idx[N_ITEMS + gi], i2 = best[i];
                    const float4* c0 = (const float4*)(codebooks + (size_t)i0 * DIM + off);
                    const float4* c1 = (const float4*)(codebooks + ((size_t)KCW + i1) * DIM + off);
                    const float4* c2 = (const float4*)(codebooks + ((size_t)2 * KCW + i2) * DIM + off);
                    float* outq = (mode == 0) ? (out + (size_t)N_ITEMS * 3) : out;
                    float4* go = (float4*)(outq + (size_t)gi * DIM + off);
                    #pragma unroll
                    for (int m = 0; m < 8; m++) {
                        float4 a = c0[m], b = c1[m], c = c2[m], o;
                        o.x = __fadd_rn(__fadd_rn(a.x, b.x), c.x);
                        o.y = __fadd_rn(__fadd_rn(a.y, b.y), c.y);
                        o.z = __fadd_rn(__fadd_rn(a.z, b.z), c.z);
                        o.w = __fadd_rn(__fadd_rn(a.w, b.w), c.w);
                        go[m] = o;
                    }
                }
            }
        }
    }
}

extern "C" void kernel_launch(void* const* d_in, const int* in_sizes, int n_in,
                              void* d_out, int out_size)
{
    const float* x   = (const float*)d_in[0];
    const float* cbk = (const float*)d_in[1];
    if (n_in >= 2 && in_sizes[0] == NCB * KCW * DIM && in_sizes[1] == N_ITEMS * DIM) {
        const float* tmp = x; x = cbk; cbk = tmp;
    }
    int mode;
    if (out_size == N_ITEMS * (3 + DIM))      mode = 0;
    else if (out_size == N_ITEMS * DIM)       mode = 1;
    else if (out_size == N_ITEMS * 3)         mode = 2;
    else                                       mode = (out_size > N_ITEMS * DIM) ? 0 : 1;

    cc_kernel<<<(NCB * KCW + 31) / 32, 32>>>(cbk);
    cudaFuncSetAttribute(rvq_kernel, cudaFuncAttributeMaxDynamicSharedMemorySize, SMEM_BYTES);
    rvq_kernel<<<GRID, NTHREADS, SMEM_BYTES>>>(x, cbk, (float*)d_out, mode);
}